// round 11
// baseline (speedup 1.0000x reference)
#include <cuda_runtime.h>
#include <stdint.h>

#define BB 4
#define NN 2048
#define EE (NN*(NN-1)/2)        // 2,096,128
#define NPAIR (NN/2)            // 1024
#define PAIRS 4                 // pairs per block
#define GX (NPAIR/PAIRS)        // 256
#define NBLKS (GX*BB)           // 1024
#define TPB 256
#define NWARP (TPB/32)

__device__ float g_partial[NBLKS];
__device__ unsigned int g_count = 0;

struct Consts {
    float f, omf;
    float qt00, qt01, qt10, qt11;   // qt[a][x] = lik(x)*pr(a)/ev(a==x)
};

__device__ __forceinline__ float edge_term(int a, float uu, float xv, const Consts& c)
{
    const float p1 = a ? c.omf : c.f;            // P(x_t = 1)
    const bool  x  = uu < p1;
    const float q0 = x ? c.qt01 : c.qt00;        // a = 0
    const float q1 = x ? c.qt11 : c.qt10;        // a = 1
    const float qt = a ? q1 : q0;
    // softplus(-|x|) = log1p(exp(-|x|)) via EX2 + LG2
    const float sp = 0.69314718056f * __log2f(1.0f + __expf(-fabsf(xv)));
    return fmaxf(xv, 0.0f) - xv * qt + sp;
}

// Thread tid owns row elements [8*tid, 8*tid+8). adj/u via aligned int4/float4.
// q row bases are only 4B-aligned, so q is loaded as two aligned float4s from
// (qrow - r), r = misalignment in floats (warp-uniform per row); the r missing
// top elements come from the next lane via shfl_down, with an in-row scalar
// patch on the boundary lane. All addresses stay inside the row.
__device__ __forceinline__ void row_sum(const int*   __restrict__ arow,
                                        const float* __restrict__ urow,
                                        const float* __restrict__ qrow,
                                        int len, int tid, const Consts& c,
                                        float& s0, float& s1, float& s2, float& s3)
{
    const int g    = tid * 8;
    const int lane = tid & 31;
    const bool full = (g + 8 <= len);

    const unsigned fm = __ballot_sync(0xFFFFFFFFu, full);
    const bool have_next = (lane < 31) && ((fm >> (lane + 1)) & 1u);

    const int r = (int)(((uintptr_t)qrow >> 2) & 3u);   // row base misalignment (floats)
    const float* qa = qrow - r;                          // 16B-aligned

    int4   a0 = {0,0,0,0}, a1 = {0,0,0,0};
    float4 u0 = {0,0,0,0}, u1 = {0,0,0,0};
    float4 lo = {0,0,0,0}, hi = {0,0,0,0};

    if (full) {
        a0 = *reinterpret_cast<const int4*>(arow + g);
        a1 = *reinterpret_cast<const int4*>(arow + g + 4);
        u0 = *reinterpret_cast<const float4*>(urow + g);
        u1 = *reinterpret_cast<const float4*>(urow + g + 4);
        lo = *reinterpret_cast<const float4*>(qa + g);       // qrow[g-r .. g+4-r)
        hi = *reinterpret_cast<const float4*>(qa + g + 4);   // qrow[g+4-r .. g+8-r)
    }
    // Missing top-r elements live in the next lane's lo.{x,y,z}.
    const float m0 = __shfl_down_sync(0xFFFFFFFFu, lo.x, 1);
    const float m1 = __shfl_down_sync(0xFFFFFFFFu, lo.y, 1);
    const float m2 = __shfl_down_sync(0xFFFFFFFFu, lo.z, 1);

    float q0, q1, q2, q3, q4, q5, q6, q7;
    switch (r) {   // warp-uniform branch
    case 0:
        q0 = lo.x; q1 = lo.y; q2 = lo.z; q3 = lo.w;
        q4 = hi.x; q5 = hi.y; q6 = hi.z; q7 = hi.w;
        break;
    case 1:
        q0 = lo.y; q1 = lo.z; q2 = lo.w; q3 = hi.x;
        q4 = hi.y; q5 = hi.z; q6 = hi.w;
        q7 = have_next ? m0 : (full ? qrow[g + 7] : 0.0f);
        break;
    case 2:
        q0 = lo.z; q1 = lo.w; q2 = hi.x; q3 = hi.y;
        q4 = hi.z; q5 = hi.w;
        q6 = have_next ? m0 : (full ? qrow[g + 6] : 0.0f);
        q7 = have_next ? m1 : (full ? qrow[g + 7] : 0.0f);
        break;
    default: // r == 3
        q0 = lo.w; q1 = hi.x; q2 = hi.y; q3 = hi.z;
        q4 = hi.w;
        q5 = have_next ? m0 : (full ? qrow[g + 5] : 0.0f);
        q6 = have_next ? m1 : (full ? qrow[g + 6] : 0.0f);
        q7 = have_next ? m2 : (full ? qrow[g + 7] : 0.0f);
        break;
    }

    if (full) {
        s0 += edge_term(a0.x, u0.x, q0, c);
        s1 += edge_term(a0.y, u0.y, q1, c);
        s2 += edge_term(a0.z, u0.z, q2, c);
        s3 += edge_term(a0.w, u0.w, q3, c);
        s0 += edge_term(a1.x, u1.x, q4, c);
        s1 += edge_term(a1.y, u1.y, q5, c);
        s2 += edge_term(a1.z, u1.z, q6, c);
        s3 += edge_term(a1.w, u1.w, q7, c);
    } else if (g < len) {
        float s = 0.0f;
        for (int j = g; j < len; j++)
            s += edge_term(arow[j], urow[j], qrow[j], c);
        s0 += s;
    }
}

__global__ __launch_bounds__(TPB) void diffusion_fused_kernel(
    const int*   __restrict__ adj,   // [B, N, N] int32
    const int*   __restrict__ t,     // [B]
    const float* __restrict__ u,     // [B, N, N]
    const float* __restrict__ q,     // [B, E]
    float* __restrict__ out)
{
    const int b   = blockIdx.y;
    const int tid = threadIdx.x;

    // Per-batch flip probabilities: f = 0.5*(1 - 0.98^(t+1)); t-1 wraps to 999.
    const int tb = t[b];
    const double L2_098 = -0.0291463456595169;   // log2(0.98)
    const float pw  = exp2f((float)((double)(tb + 1) * L2_098));
    const int   tp  = (tb == 0) ? 999 : (tb - 1);
    const float pwp = exp2f((float)((double)(tp + 1) * L2_098));

    Consts c;
    c.f   = 0.5f * (1.0f - pw);
    c.omf = 1.0f - c.f;
    const float fp   = 0.5f * (1.0f - pwp);
    const float omfp = 1.0f - fp;
    const float rf   = __fdividef(1.0f, c.f);
    const float romf = __fdividef(1.0f, c.omf);
    // qt[a][x] = lik(x) * pr(a) / ev(a==x);  ev: equal -> omf, diff -> f
    c.qt00 = 0.01f * fp   * romf;
    c.qt01 = 0.99f * fp   * rf;
    c.qt10 = 0.01f * omfp * rf;
    c.qt11 = 0.99f * omfp * romf;

    const size_t bnn = (size_t)b * NN * NN;
    const size_t bee = (size_t)b * EE;
    const int*   adjb = adj + bnn;
    const float* ub   = u + bnn;
    const float* qb   = q + bee;

    float s0 = 0.0f, s1 = 0.0f, s2 = 0.0f, s3 = 0.0f;

    #pragma unroll 1
    for (int m = 0; m < PAIRS; m++) {
        const int p  = blockIdx.x * PAIRS + m;
        const int i1 = p;              // short row
        const int i2 = NN - 1 - p;     // long row (i1 + i2 = 2047)
        row_sum(adjb + (size_t)i1 * NN, ub + (size_t)i1 * NN,
                qb + ((size_t)i1 * (size_t)(i1 - 1)) / 2, i1, tid, c, s0, s1, s2, s3);
        row_sum(adjb + (size_t)i2 * NN, ub + (size_t)i2 * NN,
                qb + ((size_t)i2 * (size_t)(i2 - 1)) / 2, i2, tid, c, s0, s1, s2, s3);
    }

    float s = (s0 + s1) + (s2 + s3);
    #pragma unroll
    for (int o = 16; o > 0; o >>= 1)
        s += __shfl_xor_sync(0xFFFFFFFFu, s, o);

    __shared__ float wsum[NWARP];
    __shared__ bool  isLast;
    const int wid = tid >> 5, lid = tid & 31;
    if (lid == 0) wsum[wid] = s;
    __syncthreads();

    if (tid == 0) {
        float bs = 0.0f;
        #pragma unroll
        for (int w = 0; w < NWARP; w++) bs += wsum[w];
        g_partial[blockIdx.y * gridDim.x + blockIdx.x] = bs;
        __threadfence();
        unsigned int old = atomicAdd(&g_count, 1u);
        isLast = (old == (unsigned)(NBLKS - 1));
    }
    __syncthreads();

    if (isLast) {
        __shared__ double dsum[TPB];
        double ds = 0.0;
        for (int idx = tid; idx < NBLKS; idx += TPB)
            ds += (double)g_partial[idx];
        dsum[tid] = ds;
        __syncthreads();
        #pragma unroll
        for (int o = TPB / 2; o > 0; o >>= 1) {
            if (tid < o) dsum[tid] += dsum[tid + o];
            __syncthreads();
        }
        if (tid == 0) {
            out[0] = (float)(dsum[0] / ((double)BB * (double)EE));
            g_count = 0;   // reset for next graph replay
        }
    }
}

extern "C" void kernel_launch(void* const* d_in, const int* in_sizes, int n_in,
                              void* d_out, int out_size)
{
    const int*   adj = (const int*)  d_in[0];
    const int*   t   = (const int*)  d_in[1];
    const float* u   = (const float*)d_in[2];
    const float* q   = (const float*)d_in[3];
    float* out = (float*)d_out;

    dim3 grid(GX, BB);
    diffusion_fused_kernel<<<grid, TPB>>>(adj, t, u, q, out);
}